// round 4
// baseline (speedup 1.0000x reference)
#include <cuda_runtime.h>

// x1, x2: [N, D] fp32, N=8192, D=1024 row-major.
// ort = dot(colsum(x1), colsum(x2)) / (N*N)

static constexpr int D    = 1024;
static constexpr int D4   = D / 4;     // 256 float4 per row
static constexpr int NB   = 592;       // grid = 148 SMs * 4 (exactly one wave)
static constexpr int PH2  = 32;        // phase-2 worker blocks (last 32 arrivals)

// Scratch (__device__ globals; no allocation allowed)
__device__ float    g_part1[NB * D];   // 2.42 MB
__device__ float    g_part2[NB * D];   // 2.42 MB
__device__ double   g_acc;
__device__ unsigned g_bar  = 0;        // arrival counter (reset by finalizer)
__device__ unsigned g_done = 0;        // phase-2 completion counter

__device__ __forceinline__ void acc4(float4& a, const float4 v) {
    a.x += v.x; a.y += v.y; a.z += v.z; a.w += v.w;
}

__global__ __launch_bounds__(256, 4) void ortho_fused(
    const float4* __restrict__ x1,
    const float4* __restrict__ x2,
    int nrows,
    float* __restrict__ out,
    double inv_count)
{
    const int t = threadIdx.x;
    const int b = blockIdx.x;

    if (b == 0 && t == 0) g_acc = 0.0;   // ordered before b0's arrive-ticket

    // ── Phase 1: per-block partial column sums (8 batched independent LDG.128)
    {
        const size_t stride = (size_t)NB * D4;
        size_t off = (size_t)b * D4 + t;

        float4 a10 = make_float4(0.f,0.f,0.f,0.f), a11 = a10;
        float4 a20 = a10, a21 = a10;

        int r = b;
        for (; r + 3 * NB < nrows; r += 4 * NB, off += 4 * stride) {
            const float4 u0 = __ldg(x1 + off);
            const float4 u1 = __ldg(x1 + off +     stride);
            const float4 u2 = __ldg(x1 + off + 2 * stride);
            const float4 u3 = __ldg(x1 + off + 3 * stride);
            const float4 w0 = __ldg(x2 + off);
            const float4 w1 = __ldg(x2 + off +     stride);
            const float4 w2 = __ldg(x2 + off + 2 * stride);
            const float4 w3 = __ldg(x2 + off + 3 * stride);
            acc4(a10, u0); acc4(a11, u1); acc4(a10, u2); acc4(a11, u3);
            acc4(a20, w0); acc4(a21, w1); acc4(a20, w2); acc4(a21, w3);
        }
        for (; r < nrows; r += NB, off += stride) {
            acc4(a10, __ldg(x1 + off));
            acc4(a20, __ldg(x2 + off));
        }
        acc4(a10, a11);
        acc4(a20, a21);
        ((float4*)g_part1)[(size_t)b * D4 + t] = a10;
        ((float4*)g_part2)[(size_t)b * D4 + t] = a20;
    }

    // ── Arrival: make partials globally visible, take a ticket.
    __threadfence();
    __syncthreads();
    __shared__ unsigned s_ticket;
    if (t == 0) s_ticket = atomicAdd(&g_bar, 1u);
    __syncthreads();
    const unsigned ticket = s_ticket;

    if (ticket < NB - PH2) return;       // early blocks exit; last 32 do phase 2
    const int g = (int)(ticket - (NB - PH2));   // column-group 0..31

    if (t == 0) {
        while (*(volatile unsigned*)&g_bar != NB) __nanosleep(64);
        __threadfence();                 // acquire: order partial reads after spin
    }
    __syncthreads();

    // ── Phase 2: finish colsums for 8 float4-cols (coalesced), dot, finalize.
    // lane layout: col4 = t&7 (contiguous 128B per 8 lanes), rl = t>>3 (row lane)
    const int col4 = t & 7;
    const int rl   = t >> 3;             // 0..31
    const int cv   = g * 8 + col4;       // global float4 column

    const float4* p1 = (const float4*)g_part1;
    const float4* p2 = (const float4*)g_part2;

    float4 s1 = make_float4(0.f,0.f,0.f,0.f);
    float4 s2 = s1;
    for (int j = rl; j < NB; j += 32) {
        acc4(s1, p1[(size_t)j * D4 + cv]);
        acc4(s2, p2[(size_t)j * D4 + cv]);
    }

    // warp-level reduce over rl (offsets 16, 8 preserve col4 = lane&7)
    #pragma unroll
    for (int o = 16; o >= 8; o >>= 1) {
        s1.x += __shfl_down_sync(0xFFFFFFFFu, s1.x, o);
        s1.y += __shfl_down_sync(0xFFFFFFFFu, s1.y, o);
        s1.z += __shfl_down_sync(0xFFFFFFFFu, s1.z, o);
        s1.w += __shfl_down_sync(0xFFFFFFFFu, s1.w, o);
        s2.x += __shfl_down_sync(0xFFFFFFFFu, s2.x, o);
        s2.y += __shfl_down_sync(0xFFFFFFFFu, s2.y, o);
        s2.z += __shfl_down_sync(0xFFFFFFFFu, s2.z, o);
        s2.w += __shfl_down_sync(0xFFFFFFFFu, s2.w, o);
    }

    __shared__ float4 sh1[8][8], sh2[8][8];   // [warp][col4]
    const int warp = t >> 5, lane = t & 31;
    if (lane < 8) { sh1[warp][lane] = s1; sh2[warp][lane] = s2; }
    __syncthreads();

    if (warp == 0) {
        // lane = w*8 + c covers warps 0..3; fold warps 4..7 on load
        const int w = lane >> 3, c = lane & 7;
        float4 v1 = sh1[w][c], v2 = sh2[w][c];
        acc4(v1, sh1[w + 4][c]);
        acc4(v2, sh2[w + 4][c]);
        #pragma unroll
        for (int o = 16; o >= 8; o >>= 1) {
            v1.x += __shfl_down_sync(0xFFFFFFFFu, v1.x, o);
            v1.y += __shfl_down_sync(0xFFFFFFFFu, v1.y, o);
            v1.z += __shfl_down_sync(0xFFFFFFFFu, v1.z, o);
            v1.w += __shfl_down_sync(0xFFFFFFFFu, v1.w, o);
            v2.x += __shfl_down_sync(0xFFFFFFFFu, v2.x, o);
            v2.y += __shfl_down_sync(0xFFFFFFFFu, v2.y, o);
            v2.z += __shfl_down_sync(0xFFFFFFFFu, v2.z, o);
            v2.w += __shfl_down_sync(0xFFFFFFFFu, v2.w, o);
        }
        // lanes 0..7 now hold COMPLETE colsums for cols cv = g*8 + lane
        double d = (double)v1.x * (double)v2.x
                 + (double)v1.y * (double)v2.y
                 + (double)v1.z * (double)v2.z
                 + (double)v1.w * (double)v2.w;
        // reduce over the 8-lane group only (width=8 keeps lanes >=8 out)
        #pragma unroll
        for (int o = 4; o > 0; o >>= 1)
            d += __shfl_down_sync(0xFFFFFFFFu, d, o, 8);

        if (lane == 0) {
            atomicAdd(&g_acc, d);
            __threadfence();
            const unsigned dt = atomicAdd(&g_done, 1u);
            if (dt == PH2 - 1) {
                out[0] = (float)(*(volatile double*)&g_acc * inv_count);
                g_bar  = 0;              // reset for next graph replay
                g_done = 0;
            }
        }
    }
}

extern "C" void kernel_launch(void* const* d_in, const int* in_sizes, int n_in,
                              void* d_out, int out_size)
{
    const float4* x1 = (const float4*)d_in[0];
    const float4* x2 = (const float4*)d_in[1];
    float* out = (float*)d_out;

    const int rows1 = in_sizes[0] / D;   // 8192
    const int rows2 = in_sizes[1] / D;   // 8192
    const double inv_count = 1.0 / ((double)rows1 * (double)rows2);

    ortho_fused<<<NB, 256>>>(x1, x2, rows1, out, inv_count);
}